// round 16
// baseline (speedup 1.0000x reference)
#include <cuda_runtime.h>
#include <cuda_fp16.h>
#include <float.h>

#define CCH   512
#define HH    38
#define WW    63
#define HWN   (HH*WW)          /* 2394 */
#define NROI  1024
#define PRE   14               /* pre-pool grid 14x14 */
#define PS    7
#define TSTRIDE 257            /* 256 half2-words + 1 pad: conflict-free flush */
#define SMEM_BYTES (49*TSTRIDE*4)  /* 50372 B */

// HWC-transposed fp16 feature map scratch (2.45 MB, L2-resident).
__device__ __half g_hwc_h[HWN * CCH];

// ---------------------------------------------------------------------------
// Kernel 1: CHW f32 -> HWC f16 transpose; packs 2 channels per 32-bit store.
// ---------------------------------------------------------------------------
__global__ void transpose_kernel(const float* __restrict__ src) {
    __shared__ float t[32][33];
    int hw0 = blockIdx.x * 32;
    int c0  = blockIdx.y * 32;

    int hw = hw0 + threadIdx.x;
#pragma unroll
    for (int dy = 0; dy < 32; dy += 8) {
        int c = c0 + threadIdx.y + dy;
        if (hw < HWN && c < CCH)
            t[threadIdx.y + dy][threadIdx.x] = src[c * HWN + hw];
    }
    __syncthreads();

    unsigned* __restrict__ dstw = reinterpret_cast<unsigned*>(g_hwc_h);
    int lin = threadIdx.y * 32 + threadIdx.x;       // 0..255
#pragma unroll
    for (int j = lin; j < 512; j += 256) {
        int wc  = j & 15;                           // word-col within tile
        int hhl = j >> 4;                           // hw within tile
        int hh  = hw0 + hhl;
        if (hh < HWN) {
            __half2 v = __floats2half2_rn(t[2 * wc][hhl], t[2 * wc + 1][hhl]);
            dstw[hh * (CCH / 2) + (c0 >> 1) + wc] = reinterpret_cast<unsigned&>(v);
        }
    }
}

// ---------------------------------------------------------------------------
// 8 channels as 4x half2
struct H8 { __half2 a, b, c, d; };

__device__ __forceinline__ H8 lerpH(H8 p, H8 q, __half2 w) {
    H8 r;
    r.a = __hfma2(__hsub2(q.a, p.a), w, p.a);
    r.b = __hfma2(__hsub2(q.b, p.b), w, p.b);
    r.c = __hfma2(__hsub2(q.c, p.c), w, p.c);
    r.d = __hfma2(__hsub2(q.d, p.d), w, p.d);
    return r;
}
// running max with half2 0/1 mask applied via HMUL2 (fma pipe)
__device__ __forceinline__ void maxH(H8& m, H8 v, __half2 mk) {
    m.a = __hmax2(m.a, __hmul2(v.a, mk));
    m.b = __hmax2(m.b, __hmul2(v.b, mk));
    m.c = __hmax2(m.c, __hmul2(v.c, mk));
    m.d = __hmax2(m.d, __hmul2(v.d, mk));
}

// ---------------------------------------------------------------------------
// Kernel 2: per-roi crop-and-resize (bilinear 14x14) + 2x2 maxpool -> 7x7.
// 8 groups x 64 lanes; group g works a CONTIGUOUS column-major cell range
// (group 0: 7 cells, groups 1-7: 6 cells), so x-coefficients are hoisted and
// reloaded at most once per group (uniform branch). All groups active.
// ---------------------------------------------------------------------------
__global__ __launch_bounds__(512, 2)
void roi_kernel(const float* __restrict__ rois, float* __restrict__ out) {
    extern __shared__ unsigned tile_u[];      // [49][TSTRIDE] half2 words

    // stage-1: per-sample
    __shared__ int     sy0[PRE], sy1[PRE], sx0[PRE], sx1[PRE];
    __shared__ float   swx_f[PRE];
    __shared__ __half2 swy[PRE];
    __shared__ unsigned svy[PRE], svx[PRE];   // 0x3C003C00 (1.0h2) or 0
    // stage-2: per pooled cell (premultiplied offsets in uint4/8-channel units)
    __shared__ int     yR0[PS], yR1[PS], yR2[PS], yR3[PS], yCs[PS];
    __shared__ unsigned yVa[PS], yVb[PS];
    __shared__ int     xC0[PS], xC1[PS], xC2[PS], xC3[PS], xCs[PS];
    __shared__ __half2 xWa[PS], xWb[PS];
    __shared__ unsigned xVa[PS], xVb[PS];

    const int r   = blockIdx.x;
    const int tid = threadIdx.x;

    // --- stage 1 (warp 0): per-axis coords / weights / validity (ref math) ---
    if (tid < 32) {
        if (tid < 2 * PRE) {
            bool isx = tid >= PRE;
            int  i   = isx ? tid - PRE : tid;
            float lo    = rois[5 * r + (isx ? 1 : 2)];
            float hi    = rois[5 * r + (isx ? 3 : 4)];
            float dimm1 = isx ? (float)(WW - 1) : (float)(HH - 1);
            float an = lo * 0.0625f / dimm1;
            float bn = hi * 0.0625f / dimm1;
            float t  = (float)i / 13.0f;
            float v  = (an + t * (bn - an)) * dimm1;
            float f  = floorf(v);
            int p0   = (int)f;
            int lim  = (int)dimm1;
            int q0   = min(max(p0, 0), lim);
            int q1   = min(max(p0 + 1, 0), lim);
            float w  = v - f;
            unsigned ok = (v >= 0.0f && v <= dimm1) ? 0x3C003C00u : 0u;
            if (isx) { sx0[i] = q0; sx1[i] = q1; swx_f[i] = w; svx[i] = ok; }
            else     { sy0[i] = q0; sy1[i] = q1;
                       swy[i] = __float2half2_rn(w); svy[i] = ok; }
        }
        __syncwarp();
        if (tid < 2 * PS) {
            bool isx = tid >= PS;
            int  q   = isx ? tid - PS : tid;
            int  i = 2 * q, j = 2 * q + 1;
            if (!isx) {
                int R0 = sy0[i], R1 = sy1[i], R2 = sy0[j], R3 = sy1[j];
                yCs[q] = (R2 == R0) ? 0 : ((R2 == R1) ? 1 : 2);
                yR0[q] = R0 * (WW * 64); yR1[q] = R1 * (WW * 64);
                yR2[q] = R2 * (WW * 64); yR3[q] = R3 * (WW * 64);
                yVa[q] = svy[i]; yVb[q] = svy[j];
            } else {
                int C0 = sx0[i], C1 = sx1[i], C2 = sx0[j], C3 = sx1[j];
                xCs[q] = (C2 == C0) ? 0 : ((C2 == C1) ? 1 : 2);
                xC0[q] = C0 * 64; xC1[q] = C1 * 64;
                xC2[q] = C2 * 64; xC3[q] = C3 * 64;
                xWa[q] = __float2half2_rn(swx_f[i]);
                xWb[q] = __float2half2_rn(swx_f[j]);
                xVa[q] = svx[i]; xVb[q] = svx[j];
            }
        }
    }
    __syncthreads();

    const int g  = tid >> 6;                      // group 0..7
    const int c8 = tid & 63;                      // 8-channel lane index
    const uint4* __restrict__ base = (const uint4*)g_hwc_h + c8;

    auto ldc = [&](int off) -> H8 {
        uint4 v = base[off];
        H8 h;
        h.a = reinterpret_cast<__half2&>(v.x);
        h.b = reinterpret_cast<__half2&>(v.y);
        h.c = reinterpret_cast<__half2&>(v.z);
        h.d = reinterpret_cast<__half2&>(v.w);
        return h;
    };

    const unsigned NEGINF2 = 0xFC00FC00u;         // half2(-inf,-inf)

    // contiguous column-major ranges: group 0 -> cells [0,7), g>=1 -> [6g+1, 6g+7)
    int k    = (g == 0) ? 0 : 6 * g + 1;
    int kEnd = (g == 0) ? 7 : 6 * g + 7;
    int px = k / 7;
    int py = k - px * 7;

    // hoisted x-coefficients for current column (reloaded on column change)
    int     c0, c1, c2, c3, xcs;
    __half2 wxa, wxb, mxa, mxb;
    auto loadx = [&](int p) {
        c0 = xC0[p]; c1 = xC1[p]; c2 = xC2[p]; c3 = xC3[p];
        xcs = xCs[p];
        wxa = xWa[p]; wxb = xWb[p];
        mxa = reinterpret_cast<const __half2&>(xVa[p]);
        mxb = reinterpret_cast<const __half2&>(xVb[p]);
    };
    loadx(px);

    // horizontal interp for one row, deduping shared columns (uniform branch)
    auto hx_row = [&](int roff, H8& ha, H8& hb) {
        if (xcs == 0) {             // 2 unique cols
            H8 g0 = ldc(roff + c0);
            H8 g1 = ldc(roff + c1);
            ha = lerpH(g0, g1, wxa);
            hb = lerpH(g0, g1, wxb);
        } else if (xcs == 1) {      // 3 unique cols
            H8 g0 = ldc(roff + c0);
            H8 g1 = ldc(roff + c1);
            H8 g3 = ldc(roff + c3);
            ha = lerpH(g0, g1, wxa);
            hb = lerpH(g1, g3, wxb);
        } else {                    // 4 unique cols
            H8 g0 = ldc(roff + c0);
            H8 g1 = ldc(roff + c1);
            H8 g2 = ldc(roff + c2);
            H8 g3 = ldc(roff + c3);
            ha = lerpH(g0, g1, wxa);
            hb = lerpH(g2, g3, wxb);
        }
    };

    for (; k < kEnd; ++k) {
        const int     r0 = yR0[py], r1 = yR1[py], r2 = yR2[py], r3 = yR3[py];
        const int     ycs = yCs[py];
        const __half2 wya = swy[2 * py], wyb = swy[2 * py + 1];
        const __half2 mya = reinterpret_cast<const __half2&>(yVa[py]);
        const __half2 myb = reinterpret_cast<const __half2&>(yVb[py]);
        const __half2 maa = __hmul2(mya, mxa);
        const __half2 mab = __hmul2(mya, mxb);
        const __half2 mba = __hmul2(myb, mxa);
        const __half2 mbb = __hmul2(myb, mxb);

        H8 m;
        m.a = reinterpret_cast<const __half2&>(NEGINF2);
        m.b = m.a; m.c = m.a; m.d = m.a;

        H8 h0a, h0b, h1a, h1b;
        hx_row(r0, h0a, h0b);
        hx_row(r1, h1a, h1b);
        maxH(m, lerpH(h0a, h1a, wya), maa);
        maxH(m, lerpH(h0b, h1b, wya), mab);

        H8 h2a, h2b, h3a, h3b;
        if (ycs == 0) {                 // reuse both rows
            h2a = h0a; h2b = h0b; h3a = h1a; h3b = h1b;
        } else if (ycs == 1) {          // reuse one row
            h2a = h1a; h2b = h1b;
            hx_row(r3, h3a, h3b);
        } else {
            hx_row(r2, h2a, h2b);
            hx_row(r3, h3a, h3b);
        }
        maxH(m, lerpH(h2a, h3a, wyb), mba);
        maxH(m, lerpH(h2b, h3b, wyb), mbb);

        // stage half2 words at raster pos = py*7 + px
        int pos = py * 7 + px;
        unsigned* st = tile_u + pos * TSTRIDE + c8;
        st[0]   = reinterpret_cast<unsigned&>(m.a);
        st[64]  = reinterpret_cast<unsigned&>(m.b);
        st[128] = reinterpret_cast<unsigned&>(m.c);
        st[192] = reinterpret_cast<unsigned&>(m.d);

        ++py;
        if (py == 7) { py = 0; ++px; if (k + 1 < kEnd) loadx(px); }
    }
    __syncthreads();

    // --- flush by channel pairs: word (P,pos) -> out[2P*49+pos], [..+49] ---
    // col(P) = (P>>2) + ((P&3)<<6); reads bank-stride 1; STG coalesced.
    float* __restrict__ dst = out + (size_t)r * (CCH * 49);
    int kk = tid;
    int P = tid / 49;
    int pos2 = tid - P * 49;
    while (kk < 256 * 49) {
        int col = (P >> 2) + ((P & 3) << 6);
        unsigned w = tile_u[pos2 * TSTRIDE + col];
        float2 f = __half22float2(reinterpret_cast<__half2&>(w));
        int o = P * 98 + pos2;
        dst[o]      = f.x;
        dst[o + 49] = f.y;
        kk += 512; pos2 += 22; P += 10;    // 512 = 10*49 + 22
        if (pos2 >= 49) { pos2 -= 49; ++P; }
    }
}

// ---------------------------------------------------------------------------
extern "C" void kernel_launch(void* const* d_in, const int* in_sizes, int n_in,
                              void* d_out, int out_size) {
    const float* bottom;
    const float* rois;
    if (n_in >= 2 && in_sizes[0] == 5 * NROI) {
        rois   = (const float*)d_in[0];
        bottom = (const float*)d_in[1];
    } else {
        bottom = (const float*)d_in[0];
        rois   = (const float*)d_in[1];
    }
    float* out = (float*)d_out;

    cudaFuncSetAttribute(roi_kernel,
                         cudaFuncAttributeMaxDynamicSharedMemorySize, SMEM_BYTES);

    dim3 tb(32, 8);
    dim3 tg((HWN + 31) / 32, (CCH + 31) / 32);
    transpose_kernel<<<tg, tb>>>(bottom);
    roi_kernel<<<NROI, 512, SMEM_BYTES>>>(rois, out);
}

// round 17
// speedup vs baseline: 1.1058x; 1.1058x over previous
#include <cuda_runtime.h>
#include <cuda_fp16.h>
#include <float.h>

#define CCH   512
#define HH    38
#define WW    63
#define HWN   (HH*WW)          /* 2394 */
#define NROI  1024
#define PRE   14               /* pre-pool grid 14x14 */
#define PS    7
#define TSTRIDE 257            /* 256 half2-words + 1 pad: conflict-free flush */
#define SMEM_BYTES (49*TSTRIDE*4)  /* 50372 B */

// HWC-transposed fp16 feature map scratch (2.45 MB, L2-resident).
__device__ __half g_hwc_h[HWN * CCH];

// ---------------------------------------------------------------------------
// Kernel 1: CHW f32 -> HWC f16 transpose; packs 2 channels per 32-bit store.
// ---------------------------------------------------------------------------
__global__ void transpose_kernel(const float* __restrict__ src) {
    __shared__ float t[32][33];
    int hw0 = blockIdx.x * 32;
    int c0  = blockIdx.y * 32;

    int hw = hw0 + threadIdx.x;
#pragma unroll
    for (int dy = 0; dy < 32; dy += 8) {
        int c = c0 + threadIdx.y + dy;
        if (hw < HWN && c < CCH)
            t[threadIdx.y + dy][threadIdx.x] = src[c * HWN + hw];
    }
    __syncthreads();

    unsigned* __restrict__ dstw = reinterpret_cast<unsigned*>(g_hwc_h);
    int lin = threadIdx.y * 32 + threadIdx.x;       // 0..255
#pragma unroll
    for (int j = lin; j < 512; j += 256) {
        int wc  = j & 15;                           // word-col within tile
        int hhl = j >> 4;                           // hw within tile
        int hh  = hw0 + hhl;
        if (hh < HWN) {
            __half2 v = __floats2half2_rn(t[2 * wc][hhl], t[2 * wc + 1][hhl]);
            dstw[hh * (CCH / 2) + (c0 >> 1) + wc] = reinterpret_cast<unsigned&>(v);
        }
    }
}

// ---------------------------------------------------------------------------
// 8 channels as 4x half2
struct H8 { __half2 a, b, c, d; };

__device__ __forceinline__ H8 lerpH(H8 p, H8 q, __half2 w) {
    H8 r;
    r.a = __hfma2(__hsub2(q.a, p.a), w, p.a);
    r.b = __hfma2(__hsub2(q.b, p.b), w, p.b);
    r.c = __hfma2(__hsub2(q.c, p.c), w, p.c);
    r.d = __hfma2(__hsub2(q.d, p.d), w, p.d);
    return r;
}
// running max with half2 0/1 mask applied via HMUL2 (fma pipe)
__device__ __forceinline__ void maxH(H8& m, H8 v, __half2 mk) {
    m.a = __hmax2(m.a, __hmul2(v.a, mk));
    m.b = __hmax2(m.b, __hmul2(v.b, mk));
    m.c = __hmax2(m.c, __hmul2(v.c, mk));
    m.d = __hmax2(m.d, __hmul2(v.d, mk));
}

// ---------------------------------------------------------------------------
// Kernel 2: per-roi crop-and-resize (bilinear 14x14) + 2x2 maxpool -> 7x7.
// 49 cells = 7 columns x 6 rows + row 6. Groups 0-6: fixed column px=g
// (x-coefficients hoisted), rows 0-5. Group 7: fixed row py=6
// (y-coefficients hoisted), columns 0-6. Every group active, fixed trip
// counts, no dynamic coefficient reloads.
// ---------------------------------------------------------------------------
__global__ __launch_bounds__(512, 2)
void roi_kernel(const float* __restrict__ rois, float* __restrict__ out) {
    extern __shared__ unsigned tile_u[];      // [49][TSTRIDE] half2 words

    // stage-1: per-sample
    __shared__ int     sy0[PRE], sy1[PRE], sx0[PRE], sx1[PRE];
    __shared__ float   swx_f[PRE];
    __shared__ __half2 swy[PRE];
    __shared__ unsigned svy[PRE], svx[PRE];   // 0x3C003C00 (1.0h2) or 0
    // stage-2: per pooled cell (premultiplied offsets in uint4/8-channel units)
    __shared__ int     yR0[PS], yR1[PS], yR2[PS], yR3[PS], yCs[PS];
    __shared__ unsigned yVa[PS], yVb[PS];
    __shared__ int     xC0[PS], xC1[PS], xC2[PS], xC3[PS], xCs[PS];
    __shared__ __half2 xWa[PS], xWb[PS];
    __shared__ unsigned xVa[PS], xVb[PS];

    const int r   = blockIdx.x;
    const int tid = threadIdx.x;

    // --- stage 1 (warp 0): per-axis coords / weights / validity (ref math) ---
    if (tid < 32) {
        if (tid < 2 * PRE) {
            bool isx = tid >= PRE;
            int  i   = isx ? tid - PRE : tid;
            float lo    = rois[5 * r + (isx ? 1 : 2)];
            float hi    = rois[5 * r + (isx ? 3 : 4)];
            float dimm1 = isx ? (float)(WW - 1) : (float)(HH - 1);
            float an = lo * 0.0625f / dimm1;
            float bn = hi * 0.0625f / dimm1;
            float t  = (float)i / 13.0f;
            float v  = (an + t * (bn - an)) * dimm1;
            float f  = floorf(v);
            int p0   = (int)f;
            int lim  = (int)dimm1;
            int q0   = min(max(p0, 0), lim);
            int q1   = min(max(p0 + 1, 0), lim);
            float w  = v - f;
            unsigned ok = (v >= 0.0f && v <= dimm1) ? 0x3C003C00u : 0u;
            if (isx) { sx0[i] = q0; sx1[i] = q1; swx_f[i] = w; svx[i] = ok; }
            else     { sy0[i] = q0; sy1[i] = q1;
                       swy[i] = __float2half2_rn(w); svy[i] = ok; }
        }
        __syncwarp();
        if (tid < 2 * PS) {
            bool isx = tid >= PS;
            int  q   = isx ? tid - PS : tid;
            int  i = 2 * q, j = 2 * q + 1;
            if (!isx) {
                int R0 = sy0[i], R1 = sy1[i], R2 = sy0[j], R3 = sy1[j];
                yCs[q] = (R2 == R0) ? 0 : ((R2 == R1) ? 1 : 2);
                yR0[q] = R0 * (WW * 64); yR1[q] = R1 * (WW * 64);
                yR2[q] = R2 * (WW * 64); yR3[q] = R3 * (WW * 64);
                yVa[q] = svy[i]; yVb[q] = svy[j];
            } else {
                int C0 = sx0[i], C1 = sx1[i], C2 = sx0[j], C3 = sx1[j];
                xCs[q] = (C2 == C0) ? 0 : ((C2 == C1) ? 1 : 2);
                xC0[q] = C0 * 64; xC1[q] = C1 * 64;
                xC2[q] = C2 * 64; xC3[q] = C3 * 64;
                xWa[q] = __float2half2_rn(swx_f[i]);
                xWb[q] = __float2half2_rn(swx_f[j]);
                xVa[q] = svx[i]; xVb[q] = svx[j];
            }
        }
    }
    __syncthreads();

    const int g  = tid >> 6;                      // group 0..7
    const int c8 = tid & 63;                      // 8-channel lane index
    const uint4* __restrict__ base = (const uint4*)g_hwc_h + c8;

    auto ldc = [&](int off) -> H8 {
        uint4 v = base[off];
        H8 h;
        h.a = reinterpret_cast<__half2&>(v.x);
        h.b = reinterpret_cast<__half2&>(v.y);
        h.c = reinterpret_cast<__half2&>(v.z);
        h.d = reinterpret_cast<__half2&>(v.w);
        return h;
    };

    const unsigned NEGINF2 = 0xFC00FC00u;         // half2(-inf,-inf)

    // coefficient registers, loaded per-axis (hoisted axis loads once)
    int     c0, c1, c2, c3, xcs;
    __half2 wxa, wxb, mxa, mxb;
    int     r0, r1, r2, r3, ycs;
    __half2 wya, wyb, mya, myb;

    auto loadx = [&](int p) {
        c0 = xC0[p]; c1 = xC1[p]; c2 = xC2[p]; c3 = xC3[p];
        xcs = xCs[p];
        wxa = xWa[p]; wxb = xWb[p];
        mxa = reinterpret_cast<const __half2&>(xVa[p]);
        mxb = reinterpret_cast<const __half2&>(xVb[p]);
    };
    auto loady = [&](int p) {
        r0 = yR0[p]; r1 = yR1[p]; r2 = yR2[p]; r3 = yR3[p];
        ycs = yCs[p];
        wya = swy[2 * p]; wyb = swy[2 * p + 1];
        mya = reinterpret_cast<const __half2&>(yVa[p]);
        myb = reinterpret_cast<const __half2&>(yVb[p]);
    };

    // horizontal interp for one row, deduping shared columns (uniform branch)
    auto hx_row = [&](int roff, H8& ha, H8& hb) {
        if (xcs == 0) {             // 2 unique cols
            H8 g0 = ldc(roff + c0);
            H8 g1 = ldc(roff + c1);
            ha = lerpH(g0, g1, wxa);
            hb = lerpH(g0, g1, wxb);
        } else if (xcs == 1) {      // 3 unique cols
            H8 g0 = ldc(roff + c0);
            H8 g1 = ldc(roff + c1);
            H8 g3 = ldc(roff + c3);
            ha = lerpH(g0, g1, wxa);
            hb = lerpH(g1, g3, wxb);
        } else {                    // 4 unique cols
            H8 g0 = ldc(roff + c0);
            H8 g1 = ldc(roff + c1);
            H8 g2 = ldc(roff + c2);
            H8 g3 = ldc(roff + c3);
            ha = lerpH(g0, g1, wxa);
            hb = lerpH(g2, g3, wxb);
        }
    };

    auto do_cell = [&](int pos) {
        const __half2 maa = __hmul2(mya, mxa);
        const __half2 mab = __hmul2(mya, mxb);
        const __half2 mba = __hmul2(myb, mxa);
        const __half2 mbb = __hmul2(myb, mxb);

        H8 m;
        m.a = reinterpret_cast<const __half2&>(NEGINF2);
        m.b = m.a; m.c = m.a; m.d = m.a;

        H8 h0a, h0b, h1a, h1b;
        hx_row(r0, h0a, h0b);
        hx_row(r1, h1a, h1b);
        maxH(m, lerpH(h0a, h1a, wya), maa);
        maxH(m, lerpH(h0b, h1b, wya), mab);

        H8 h2a, h2b, h3a, h3b;
        if (ycs == 0) {                 // reuse both rows
            h2a = h0a; h2b = h0b; h3a = h1a; h3b = h1b;
        } else if (ycs == 1) {          // reuse one row
            h2a = h1a; h2b = h1b;
            hx_row(r3, h3a, h3b);
        } else {
            hx_row(r2, h2a, h2b);
            hx_row(r3, h3a, h3b);
        }
        maxH(m, lerpH(h2a, h3a, wyb), mba);
        maxH(m, lerpH(h2b, h3b, wyb), mbb);

        // stage half2 words: word col = c8 + 64*w holds channels 8c8+2w, +1
        unsigned* st = tile_u + pos * TSTRIDE + c8;
        st[0]   = reinterpret_cast<unsigned&>(m.a);
        st[64]  = reinterpret_cast<unsigned&>(m.b);
        st[128] = reinterpret_cast<unsigned&>(m.c);
        st[192] = reinterpret_cast<unsigned&>(m.d);
    };

    if (g < 7) {
        // fixed column px=g (x hoisted), rows 0..5
        loadx(g);
        for (int py = 0; py < 6; ++py) {
            loady(py);
            do_cell(py * 7 + g);
        }
    } else {
        // fixed row py=6 (y hoisted), columns 0..6
        loady(6);
        for (int px = 0; px < 7; ++px) {
            loadx(px);
            do_cell(42 + px);
        }
    }
    __syncthreads();

    // --- flush by channel pairs: word (P,pos) -> out[2P*49+pos], [..+49] ---
    // col(P) = (P>>2) + ((P&3)<<6); reads bank-stride 1; STG coalesced.
    float* __restrict__ dst = out + (size_t)r * (CCH * 49);
    int kk = tid;
    int P = tid / 49;
    int pos2 = tid - P * 49;
    while (kk < 256 * 49) {
        int col = (P >> 2) + ((P & 3) << 6);
        unsigned w = tile_u[pos2 * TSTRIDE + col];
        float2 f = __half22float2(reinterpret_cast<__half2&>(w));
        int o = P * 98 + pos2;
        dst[o]      = f.x;
        dst[o + 49] = f.y;
        kk += 512; pos2 += 22; P += 10;    // 512 = 10*49 + 22
        if (pos2 >= 49) { pos2 -= 49; ++P; }
    }
}

// ---------------------------------------------------------------------------
extern "C" void kernel_launch(void* const* d_in, const int* in_sizes, int n_in,
                              void* d_out, int out_size) {
    const float* bottom;
    const float* rois;
    if (n_in >= 2 && in_sizes[0] == 5 * NROI) {
        rois   = (const float*)d_in[0];
        bottom = (const float*)d_in[1];
    } else {
        bottom = (const float*)d_in[0];
        rois   = (const float*)d_in[1];
    }
    float* out = (float*)d_out;

    cudaFuncSetAttribute(roi_kernel,
                         cudaFuncAttributeMaxDynamicSharedMemorySize, SMEM_BYTES);

    dim3 tb(32, 8);
    dim3 tg((HWN + 31) / 32, (CCH + 31) / 32);
    transpose_kernel<<<tg, tb>>>(bottom);
    roi_kernel<<<NROI, 512, SMEM_BYTES>>>(rois, out);
}